// round 9
// baseline (speedup 1.0000x reference)
#include <cuda_runtime.h>
#include <cuda_fp16.h>
#include <cstdint>

// Problem dims (fixed)
#define Bb 32
#define Cc 256
#define Hh 36
#define Ww 64
#define Nn 4096
#define Kk 2304

// Scratch: fp16 G masks [n][k] (18.9 MB) and fp16 feat [b][c][k] (37.7 MB)
__device__ __half g_G[(size_t)Nn * Kk];
__device__ __half g_F[(size_t)Bb * Cc * Kk];

__device__ __forceinline__ uint32_t smem_u32(const void* p) {
    uint32_t a;
    asm("{ .reg .u64 t; cvta.to.shared.u64 t, %1; cvt.u32.u64 %0, t; }"
        : "=r"(a) : "l"(p));
    return a;
}
__device__ __forceinline__ void mma_f16(float d[4], const uint32_t a[4], const uint32_t b0,
                                        const uint32_t b1) {
    asm volatile(
        "mma.sync.aligned.m16n8k16.row.col.f32.f16.f16.f32 "
        "{%0,%1,%2,%3}, {%4,%5,%6,%7}, {%8,%9}, {%0,%1,%2,%3};\n"
        : "+f"(d[0]), "+f"(d[1]), "+f"(d[2]), "+f"(d[3])
        : "r"(a[0]), "r"(a[1]), "r"(a[2]), "r"(a[3]), "r"(b0), "r"(b1));
}
#define LDSM4(r, addr) \
    asm volatile("ldmatrix.sync.aligned.m8n8.x4.shared.b16 {%0,%1,%2,%3}, [%4];" \
                 : "=r"((r)[0]), "=r"((r)[1]), "=r"((r)[2]), "=r"((r)[3]) \
                 : "r"(addr))
#define CP_ASYNC16(dst, src) \
    asm volatile("cp.async.cg.shared.global [%0], [%1], 16;" \
                 :: "r"((uint32_t)(dst)), "l"(src) : "memory")
#define CP_COMMIT() asm volatile("cp.async.commit_group;" ::: "memory")
#define CP_WAIT1()  asm volatile("cp.async.wait_group 1;" ::: "memory")
#define CP_WAIT0()  asm volatile("cp.async.wait_group 0;" ::: "memory")

// ---------------------------------------------------------------------------
// Kernel 0 (fused prepass):
//   blocks [0, FEAT_BLKS)        : feat fp32 -> fp16, 8 floats/thread
//   blocks [FEAT_BLKS, +Nn)      : Gaussian masks -> fp16
// ---------------------------------------------------------------------------
#define FEAT_BLKS ((Bb * Cc * Kk) / (256 * 8))   // 9216

__global__ __launch_bounds__(256)
void prepass(const float* __restrict__ feat,
             const float* __restrict__ mu,
             const float* __restrict__ logsx,
             const float* __restrict__ logsy,
             const float* __restrict__ rho) {
    if (blockIdx.x < FEAT_BLKS) {
        const size_t i = ((size_t)blockIdx.x * 256 + threadIdx.x) * 8;
        const float4 v0 = *(const float4*)(feat + i);
        const float4 v1 = *(const float4*)(feat + i + 4);
        __half2 h[4];
        h[0] = __floats2half2_rn(v0.x, v0.y);
        h[1] = __floats2half2_rn(v0.z, v0.w);
        h[2] = __floats2half2_rn(v1.x, v1.y);
        h[3] = __floats2half2_rn(v1.z, v1.w);
        *(uint4*)(g_F + i) = *(const uint4*)h;
    } else {
        const int n = blockIdx.x - FEAT_BLKS;
        const float mux = mu[2 * n];
        const float muy = mu[2 * n + 1];
        const float sx = expf(logsx[n]) + 1e-6f;
        const float sy = expf(logsy[n]) + 1e-6f;
        const float r  = tanhf(rho[n]);
        const float isx = 1.0f / sx;
        const float isy = 1.0f / sy;
        const float iden = 1.0f / (2.0f * (1.0f - r * r + 1e-6f));
        __half* Grow = g_G + (size_t)n * Kk;
        for (int k = threadIdx.x; k < Kk; k += 256) {
            const int h = k / Ww;
            const int w = k - h * Ww;
            const float x = -1.0f + w * (2.0f / (Ww - 1));
            const float y = -1.0f + h * (2.0f / (Hh - 1));
            const float xc = (x - mux) * isx;
            const float yc = (y - muy) * isy;
            const float A = xc * xc + yc * yc - 2.0f * r * xc * yc;
            Grow[k] = __float2half_rn(expf(-A * iden));
        }
    }
}

// ---------------------------------------------------------------------------
// Kernel 2: fp16 mma.sync GEMM (fp32 accumulate).
//   CTA: 128 (n) x 256 (c, full C).  K in BK=128 chunks, 2-stage cp.async.
//   8 warps = 2 (m) x 4 (n), warp tile 64x64.  Fragments via ldmatrix.x4.
//   Tiles K-major [row][128 halves], row stride 272 B (256 data + 16 pad):
//   16B-aligned for cp.async, conflict-free ldmatrix (banks 4*row mod 32).
//   ldmatrix.x4 regs: r0=(rows0-7,k0-7) r1=(rows8-15,k0-7) r2=(rows0-7,k8-15)
//   r3=(rows8-15,k8-15)  ->  B pairs (r0,r2), (r1,r3).
//   Fused epilogue: out[b,n] = sum_c D[n,c]*weight[n,c].
// ---------------------------------------------------------------------------
#define BK 128
#define NIT (Kk / BK)               // 18
#define ROWB 272                    // bytes per smem row
#define A_BYTES (128 * ROWB)        // 34816
#define B_BYTES (256 * ROWB)        // 69632
#define STAGE   (A_BYTES + B_BYTES) // 104448
#define SMEM_DYN (2 * STAGE)        // 208896

__global__ __launch_bounds__(256, 1)
void gemm_mma(const float* __restrict__ weight, float* __restrict__ out) {
    extern __shared__ char smem[];
    __shared__ float red[4][128];
    const uint32_t sb = smem_u32(smem);

    const int tid  = threadIdx.x;
    const int lane = tid & 31;
    const int wid  = tid >> 5;
    const int g    = lane >> 2;
    const int t4   = lane & 3;
    const int wm   = wid & 1;    // 0..1 : 64-row half (n)
    const int wn   = wid >> 1;   // 0..3 : 64-col quarter (c)

    const int n0 = blockIdx.x * 128;
    const int b  = blockIdx.y;

    const char* srcA0 = (const char*)(g_G + (size_t)n0 * Kk);
    const char* srcB0 = (const char*)(g_F + (size_t)b * Cc * Kk);

    // cp.async: 6144 granules of 16B per stage, 24 per thread
    #define ISSUE_STAGE(ii, ss) do {                                          \
        const uint32_t stA = sb + (ss) * STAGE;                               \
        const uint32_t stB = stA + A_BYTES;                                   \
        const char* sA = srcA0 + (size_t)(ii) * (BK * 2);                     \
        const char* sB = srcB0 + (size_t)(ii) * (BK * 2);                     \
        _Pragma("unroll")                                                     \
        for (int j = 0; j < 8; j++) {                                         \
            const int idx = tid + j * 256;                                    \
            const int r = idx >> 4, q = idx & 15;                             \
            CP_ASYNC16(stA + r * ROWB + q * 16,                               \
                       sA + (size_t)r * (Kk * 2) + q * 16);                   \
        }                                                                     \
        _Pragma("unroll")                                                     \
        for (int j = 0; j < 16; j++) {                                        \
            const int idx = tid + j * 256;                                    \
            const int c = idx >> 4, q = idx & 15;                             \
            CP_ASYNC16(stB + c * ROWB + q * 16,                               \
                       sB + (size_t)c * (Kk * 2) + q * 16);                   \
        }                                                                     \
        CP_COMMIT();                                                          \
    } while (0)

    // ldmatrix per-thread base addresses:
    // lanes 0-15 -> rows 0-15 at k-byte 0; lanes 16-31 -> rows 0-15 at k-byte 16
    const int rin = (lane & 7) + ((lane >> 3) & 1) * 8;   // 0..15
    const int kof = (lane >> 4) * 16;                     // 0 or 16 bytes
    const uint32_t aBase = sb + (wm * 64 + rin) * ROWB + kof;
    const uint32_t bBase = sb + A_BYTES + (wn * 64 + rin) * ROWB + kof;

    float acc[4][8][4];
    #pragma unroll
    for (int i = 0; i < 4; i++)
        #pragma unroll
        for (int j = 0; j < 8; j++)
            #pragma unroll
            for (int q = 0; q < 4; q++) acc[i][j][q] = 0.0f;

    ISSUE_STAGE(0, 0);
    ISSUE_STAGE(1, 1);

    #pragma unroll 1
    for (int i = 0; i < NIT; i++) {
        const int s = i & 1;
        if (i == NIT - 1) { CP_WAIT0(); } else { CP_WAIT1(); }
        __syncthreads();

        const uint32_t aS = aBase + s * STAGE;
        const uint32_t bS = bBase + s * STAGE;
        #pragma unroll
        for (int kk = 0; kk < BK; kk += 16) {
            uint32_t afr[4][4], bfr[4][4];
            #pragma unroll
            for (int mf = 0; mf < 4; mf++)
                LDSM4(afr[mf], aS + mf * (16 * ROWB) + kk * 2);
            #pragma unroll
            for (int nf2 = 0; nf2 < 4; nf2++)
                LDSM4(bfr[nf2], bS + nf2 * (16 * ROWB) + kk * 2);
            #pragma unroll
            for (int mf = 0; mf < 4; mf++)
                #pragma unroll
                for (int nf2 = 0; nf2 < 4; nf2++) {
                    mma_f16(acc[mf][nf2 * 2],     afr[mf], bfr[nf2][0], bfr[nf2][2]);
                    mma_f16(acc[mf][nf2 * 2 + 1], afr[mf], bfr[nf2][1], bfr[nf2][3]);
                }
        }

        if (i + 2 < NIT) {
            __syncthreads();           // all warps done reading stage s
            ISSUE_STAGE(i + 2, s);     // refill it
        }
    }

    // ---------------- epilogue: weight dot + cross-warp reduction ----------
    #pragma unroll
    for (int mf = 0; mf < 4; mf++) {
        const int r0 = wm * 64 + mf * 16 + g;
        const int r1 = r0 + 8;
        float p0 = 0.0f, p1 = 0.0f;
        #pragma unroll
        for (int nf = 0; nf < 8; nf++) {
            const int c = wn * 64 + nf * 8 + (t4 << 1);
            const float2 w0 = *(const float2*)(weight + (size_t)(n0 + r0) * Cc + c);
            const float2 w1 = *(const float2*)(weight + (size_t)(n0 + r1) * Cc + c);
            p0 += acc[mf][nf][0] * w0.x + acc[mf][nf][1] * w0.y;
            p1 += acc[mf][nf][2] * w1.x + acc[mf][nf][3] * w1.y;
        }
        p0 += __shfl_xor_sync(0xffffffffu, p0, 1);
        p0 += __shfl_xor_sync(0xffffffffu, p0, 2);
        p1 += __shfl_xor_sync(0xffffffffu, p1, 1);
        p1 += __shfl_xor_sync(0xffffffffu, p1, 2);
        if (t4 == 0) {
            red[wn][r0] = p0;
            red[wn][r1] = p1;
        }
    }
    __syncthreads();
    if (tid < 128) {
        const float v = red[0][tid] + red[1][tid] + red[2][tid] + red[3][tid];
        out[(size_t)b * Nn + n0 + tid] = v;
    }
}

// ---------------------------------------------------------------------------
extern "C" void kernel_launch(void* const* d_in, const int* in_sizes, int n_in,
                              void* d_out, int out_size) {
    const float* feat   = (const float*)d_in[0];
    const float* mu     = (const float*)d_in[1];
    const float* logsx  = (const float*)d_in[2];
    const float* logsy  = (const float*)d_in[3];
    const float* rho    = (const float*)d_in[4];
    const float* weight = (const float*)d_in[5];
    float* out = (float*)d_out;

    static bool attr_set = false;
    if (!attr_set) {
        cudaFuncSetAttribute(gemm_mma, cudaFuncAttributeMaxDynamicSharedMemorySize,
                             SMEM_DYN);
        attr_set = true;
    }

    prepass<<<FEAT_BLKS + Nn, 256>>>(feat, mu, logsx, logsy, rho);
    dim3 grid(Nn / 128, Bb);
    gemm_mma<<<grid, 256, SMEM_DYN>>>(weight, out);
}